// round 14
// baseline (speedup 1.0000x reference)
#include <cuda_runtime.h>
#include <cuda_fp16.h>
#include <math.h>

#define Nn 50000
#define Ee 1600000
#define INF 128
#define Hh 64
#define NSCAN ((Nn + 1023) / 1024)   // 49

// ---------------- scratch ----------------
__device__ int    g_deg[Nn];          // zero-initialized; self-cleaned by k_scan
__device__ int    g_rowstart[Nn + 1];
__device__ int    g_cursor[Nn];
__device__ int    g_srcsorted[Ee];
__device__ int    g_bsum[64];
__device__ int    g_bflag[64];        // reset by k_hist block 0 each launch
__device__ float  g_dinv[Nn];
__device__ float  g_f0[Nn * Hh];
__device__ __half g_s[Nn * Hh];
__device__ float  g_f1[Nn * Hh];
__device__ __half g_s2[Nn * Hh];
__device__ float  g_f2[Nn * Hh];

__device__ __forceinline__ float wsum(float v) {
#pragma unroll
    for (int o = 16; o; o >>= 1) v += __shfl_xor_sync(0xffffffffu, v, o);
    return v;
}

// ---------------- CSR build ----------------
__global__ void k_hist(const int* __restrict__ dst) {
    // block 0 resets the scan lookback flags (stream-ordered before k_scan)
    if (blockIdx.x == 0 && threadIdx.x < 64) g_bflag[threadIdx.x] = 0;
    int i = blockIdx.x * blockDim.x + threadIdx.x;
    if (i < Ee / 4) {
        int4 d = ((const int4*)dst)[i];
        atomicAdd(&g_deg[d.x], 1);
        atomicAdd(&g_deg[d.y], 1);
        atomicAdd(&g_deg[d.z], 1);
        atomicAdd(&g_deg[d.w], 1);
    }
}

// Single-pass scan with decoupled lookback (49 blocks, all co-resident).
// Computes rowstart/cursor/dinv, zeroes g_deg, publishes block sums via flags.
__global__ void k_scan() {
    __shared__ int wsh[32];
    __shared__ int offsh;
    int tid = threadIdx.x, lane = tid & 31, wid = tid >> 5;
    int b = blockIdx.x;
    int i = b * 1024 + tid;
    int v = (i < Nn) ? g_deg[i] : 0;
    int x = v;
#pragma unroll
    for (int o = 1; o < 32; o <<= 1) {
        int t = __shfl_up_sync(0xffffffffu, x, o);
        if (lane >= o) x += t;
    }
    if (lane == 31) wsh[wid] = x;
    __syncthreads();
    if (wid == 0) {
        int y = wsh[lane];
#pragma unroll
        for (int o = 1; o < 32; o <<= 1) {
            int t = __shfl_up_sync(0xffffffffu, y, o);
            if (lane >= o) y += t;
        }
        wsh[lane] = y;
    }
    __syncthreads();
    int incl = x + (wid ? wsh[wid - 1] : 0);   // inclusive prefix within block
    int btotal = wsh[31];

    // publish this block's total
    if (tid == 0) {
        g_bsum[b] = btotal;
        __threadfence();
        *((volatile int*)&g_bflag[b]) = 1;
    }

    // warp-parallel lookback over predecessor blocks
    if (tid < 32) {
        int off = 0;
        for (int j = tid; j < b; j += 32) {
            while (*((volatile int*)&g_bflag[j]) == 0) { }
            off += g_bsum[j];
        }
#pragma unroll
        for (int o = 16; o; o >>= 1) off += __shfl_xor_sync(0xffffffffu, off, o);
        if (tid == 0) offsh = off;
    }
    __syncthreads();
    int off = offsh;

    if (i < Nn) {
        int excl = off + incl - v;
        g_rowstart[i] = excl;
        g_cursor[i] = excl;
        g_dinv[i] = rsqrtf((float)(v > 0 ? v : 1));
        g_deg[i] = 0;                       // self-clean for next call
    }
    if (b == NSCAN - 1 && tid == 1023) g_rowstart[Nn] = off + incl;
}

__global__ void k_scatter(const int* __restrict__ src, const int* __restrict__ dst) {
    int i = blockIdx.x * blockDim.x + threadIdx.x;
    if (i < Ee / 4) {
        int4 s = ((const int4*)src)[i];
        int4 d = ((const int4*)dst)[i];
        g_srcsorted[atomicAdd(&g_cursor[d.x], 1)] = s.x;
        g_srcsorted[atomicAdd(&g_cursor[d.y], 1)] = s.y;
        g_srcsorted[atomicAdd(&g_cursor[d.z], 1)] = s.z;
        g_srcsorted[atomicAdd(&g_cursor[d.w], 1)] = s.w;
    }
}

// ---------------- f0 = relu(relu(X@W1+b1)@W2+b2)  (scalar FFMA) ----------
#define FC_SMEM_FLOATS (INF * Hh + Hh * Hh + Hh + Hh + 16 * INF + 16 * Hh)
__global__ void k_fc(const float* __restrict__ in_feat,
                     const float* __restrict__ W1, const float* __restrict__ b1,
                     const float* __restrict__ W2, const float* __restrict__ b2) {
    extern __shared__ float sm[];
    float* W1s = sm;
    float* W2s = W1s + INF * Hh;
    float* b1s = W2s + Hh * Hh;
    float* b2s = b1s + Hh;
    float* xsh = b2s + Hh;
    float* h1s = xsh + 16 * INF;

    int tid = threadIdx.x;
    for (int t = tid; t < 2048; t += 256) ((float4*)W1s)[t] = ((const float4*)W1)[t];
    for (int t = tid; t < 1024; t += 256) ((float4*)W2s)[t] = ((const float4*)W2)[t];
    if (tid < Hh) { b1s[tid] = b1[tid]; b2s[tid] = b2[tid]; }
    {
        const float4* xin = (const float4*)(in_feat + (long long)blockIdx.x * 16 * INF);
        for (int t = tid; t < 512; t += 256) ((float4*)xsh)[t] = xin[t];
    }
    __syncthreads();

    int j = tid & 63, g = tid >> 6;
    float a0 = b1s[j], a1 = a0, a2 = a0, a3 = a0;
#pragma unroll 8
    for (int i = 0; i < INF; i += 2) {
        float w0 = W1s[i * Hh + j];
        float w1 = W1s[(i + 1) * Hh + j];
        float2 x0 = *(const float2*)(xsh + (4 * g + 0) * INF + i);
        float2 x1 = *(const float2*)(xsh + (4 * g + 1) * INF + i);
        float2 x2 = *(const float2*)(xsh + (4 * g + 2) * INF + i);
        float2 x3 = *(const float2*)(xsh + (4 * g + 3) * INF + i);
        a0 += x0.x * w0 + x0.y * w1;
        a1 += x1.x * w0 + x1.y * w1;
        a2 += x2.x * w0 + x2.y * w1;
        a3 += x3.x * w0 + x3.y * w1;
    }
    h1s[(4 * g + 0) * Hh + j] = fmaxf(a0, 0.f);
    h1s[(4 * g + 1) * Hh + j] = fmaxf(a1, 0.f);
    h1s[(4 * g + 2) * Hh + j] = fmaxf(a2, 0.f);
    h1s[(4 * g + 3) * Hh + j] = fmaxf(a3, 0.f);
    __syncthreads();

    float c0 = b2s[j], c1 = c0, c2 = c0, c3 = c0;
#pragma unroll 8
    for (int i = 0; i < Hh; i += 2) {
        float w0 = W2s[i * Hh + j];
        float w1 = W2s[(i + 1) * Hh + j];
        float2 x0 = *(const float2*)(h1s + (4 * g + 0) * Hh + i);
        float2 x1 = *(const float2*)(h1s + (4 * g + 1) * Hh + i);
        float2 x2 = *(const float2*)(h1s + (4 * g + 2) * Hh + i);
        float2 x3 = *(const float2*)(h1s + (4 * g + 3) * Hh + i);
        c0 += x0.x * w0 + x0.y * w1;
        c1 += x1.x * w0 + x1.y * w1;
        c2 += x2.x * w0 + x2.y * w1;
        c3 += x3.x * w0 + x3.y * w1;
    }
    c0 = fmaxf(c0, 0.f); c1 = fmaxf(c1, 0.f);
    c2 = fmaxf(c2, 0.f); c3 = fmaxf(c3, 0.f);
    int n0 = blockIdx.x * 16 + 4 * g;
    g_f0[(n0 + 0) * Hh + j] = c0;
    g_f0[(n0 + 1) * Hh + j] = c1;
    g_f0[(n0 + 2) * Hh + j] = c2;
    g_f0[(n0 + 3) * Hh + j] = c3;
}

// ---------------- s = fp16(f0 * dinv) ----------------
__global__ void k_make_s() {
    int i = blockIdx.x * blockDim.x + threadIdx.x;
    if (i < Nn * Hh / 4) {
        float4 v = ((const float4*)g_f0)[i];
        float dv = g_dinv[i >> 4];
        __half2* Sh = (__half2*)g_s;
        Sh[2 * i]     = __floats2half2_rn(v.x * dv, v.y * dv);
        Sh[2 * i + 1] = __floats2half2_rn(v.z * dv, v.w * dv);
    }
}

// ---------------- SpMM (R9): fOut = base - dinv * (A @ sIn), fp16 gather, 8-wide ----
template <bool WRITE_S>
__global__ void k_spmm() {
    int w = threadIdx.x >> 5;
    int row = blockIdx.x * 8 + w;
    if (row >= Nn) return;
    int lane = threadIdx.x & 31;
    const __half2* S = WRITE_S ? (const __half2*)g_s : (const __half2*)g_s2;
    const float2*  B = WRITE_S ? (const float2*)g_f0 : (const float2*)g_f1;
    float2* FO = WRITE_S ? (float2*)g_f1 : (float2*)g_f2;

    int beg = __ldg(&g_rowstart[row]), end = __ldg(&g_rowstart[row + 1]);
    float ax = 0.f, ay = 0.f, bx = 0.f, by = 0.f;
    float cx = 0.f, cy = 0.f, dx = 0.f, dy = 0.f;
    int k = beg;
    for (; k + 7 < end; k += 8) {
        int s0 = __ldg(&g_srcsorted[k]);
        int s1 = __ldg(&g_srcsorted[k + 1]);
        int s2 = __ldg(&g_srcsorted[k + 2]);
        int s3 = __ldg(&g_srcsorted[k + 3]);
        int s4 = __ldg(&g_srcsorted[k + 4]);
        int s5 = __ldg(&g_srcsorted[k + 5]);
        int s6 = __ldg(&g_srcsorted[k + 6]);
        int s7 = __ldg(&g_srcsorted[k + 7]);
        float2 v0 = __half22float2(__ldg(&S[s0 * 32 + lane]));
        float2 v1 = __half22float2(__ldg(&S[s1 * 32 + lane]));
        float2 v2 = __half22float2(__ldg(&S[s2 * 32 + lane]));
        float2 v3 = __half22float2(__ldg(&S[s3 * 32 + lane]));
        float2 v4 = __half22float2(__ldg(&S[s4 * 32 + lane]));
        float2 v5 = __half22float2(__ldg(&S[s5 * 32 + lane]));
        float2 v6 = __half22float2(__ldg(&S[s6 * 32 + lane]));
        float2 v7 = __half22float2(__ldg(&S[s7 * 32 + lane]));
        ax += v0.x + v4.x; ay += v0.y + v4.y;
        bx += v1.x + v5.x; by += v1.y + v5.y;
        cx += v2.x + v6.x; cy += v2.y + v6.y;
        dx += v3.x + v7.x; dy += v3.y + v7.y;
    }
    for (; k + 1 < end; k += 2) {
        int s0 = __ldg(&g_srcsorted[k]);
        int s1 = __ldg(&g_srcsorted[k + 1]);
        float2 v0 = __half22float2(__ldg(&S[s0 * 32 + lane]));
        float2 v1 = __half22float2(__ldg(&S[s1 * 32 + lane]));
        ax += v0.x; ay += v0.y;
        bx += v1.x; by += v1.y;
    }
    if (k < end) {
        int s0 = __ldg(&g_srcsorted[k]);
        float2 v0 = __half22float2(__ldg(&S[s0 * 32 + lane]));
        ax += v0.x; ay += v0.y;
    }
    ax += bx + cx + dx;
    ay += by + cy + dy;
    float dv = g_dinv[row];
    float2 bv = B[row * 32 + lane];
    float2 f = make_float2(bv.x - dv * ax, bv.y - dv * ay);
    FO[row * 32 + lane] = f;
    if (WRITE_S) {
        ((__half2*)g_s2)[row * 32 + lane] = __floats2half2_rn(f.x * dv, f.y * dv);
    }
}

// ---------------- fusion + heads ----------------
#define FIN_SMEM_FLOATS (4096 + 8192 + 4096 + 64 + 64 + 128 + 64 + 64 + 64 + 32*128 + 32*64 + 32*64)
__global__ void k_final(const float* __restrict__ Wres, const float* __restrict__ bres,
                        const float* __restrict__ Wattn, const float* __restrict__ battn,
                        const float* __restrict__ Wf1, const float* __restrict__ bf1,
                        const float* __restrict__ Wf2, const float* __restrict__ bf2,
                        const float* __restrict__ W3, const float* __restrict__ b3,
                        const float* __restrict__ W4, const float* __restrict__ b4,
                        float* __restrict__ out) {
    extern __shared__ float sm[];
    float* Wres_s  = sm;
    float* Wf1_s   = Wres_s + 4096;
    float* W3_s    = Wf1_s + 8192;
    float* Wattn_s = W3_s + 4096;
    float* Wf2_s   = Wattn_s + 64;
    float* W4_s    = Wf2_s + 64;
    float* bres_s  = W4_s + 128;
    float* bf1_s   = bres_s + 64;
    float* b3_s    = bf1_s + 64;
    float* fin_s   = b3_s + 64;
    float* f0_s    = fin_s + 32 * 128;
    float* fu_s    = f0_s + 32 * 64;

    int tid = threadIdx.x;
    for (int t = tid; t < 1024; t += 256) ((float4*)Wres_s)[t] = ((const float4*)Wres)[t];
    for (int t = tid; t < 2048; t += 256) ((float4*)Wf1_s)[t] = ((const float4*)Wf1)[t];
    for (int t = tid; t < 1024; t += 256) ((float4*)W3_s)[t] = ((const float4*)W3)[t];
    if (tid < 64) {
        Wattn_s[tid] = Wattn[tid]; Wf2_s[tid] = Wf2[tid];
        bres_s[tid] = bres[tid];   bf1_s[tid] = bf1[tid]; b3_s[tid] = b3[tid];
    }
    if (tid < 128) W4_s[tid] = W4[tid];
    __syncthreads();

    int w = tid >> 5, l = tid & 31;

    float2 at[4], mn[4];
    const float2* F0 = (const float2*)g_f0;
    const float2* F1 = (const float2*)g_f1;
    const float2* F2 = (const float2*)g_f2;
    float2 wat = ((const float2*)Wattn_s)[l];
    float bat = battn[0];

#pragma unroll
    for (int m = 0; m < 4; m++) {
        int ln = w * 4 + m;
        int n = blockIdx.x * 32 + ln;
        int nc = (n < Nn) ? n : (Nn - 1);
        float2 f0 = F0[nc * 32 + l];
        float2 f1 = F1[nc * 32 + l];
        float2 f2 = F2[nc * 32 + l];
        ((float2*)(f0_s + ln * 64))[l] = f0;

        float2 c0 = make_float2(3.f*f0.x - 3.f*f1.x + 0.75f*f2.x,
                                3.f*f0.y - 3.f*f1.y + 0.75f*f2.y);
        float2 c1 = make_float2(3.f*f1.x - 1.5f*f2.x, 3.f*f1.y - 1.5f*f2.y);
        float2 c2 = make_float2(0.75f*f2.x, 0.75f*f2.y);

        float s0 = wsum(c0.x*wat.x + c0.y*wat.y) + bat;
        float s1 = wsum(c1.x*wat.x + c1.y*wat.y) + bat;
        float s2 = wsum(c2.x*wat.x + c2.y*wat.y) + bat;
        float mx = fmaxf(s0, fmaxf(s1, s2));
        float e0 = expf(s0 - mx), e1 = expf(s1 - mx), e2 = expf(s2 - mx);
        float inv = 1.f / (e0 + e1 + e2);
        float w0 = e0*inv, w1 = e1*inv, w2 = e2*inv;

        at[m] = make_float2(w0*c0.x + w1*c1.x + w2*c2.x,
                            w0*c0.y + w1*c1.y + w2*c2.y);
        const float third = 1.f / 3.f;
        mn[m] = make_float2((c0.x + c1.x + c2.x)*third, (c0.y + c1.y + c2.y)*third);

        float* fin = fin_s + ln * 128;
        ((float2*)fin)[l] = at[m];
        ((float2*)(fin + 64))[l] = mn[m];
    }
    __syncwarp();

    float2 res[4];
    {
        float2 bv = ((const float2*)bres_s)[l];
#pragma unroll
        for (int m = 0; m < 4; m++) res[m] = bv;
    }
#pragma unroll 4
    for (int i = 0; i < 64; i += 2) {
        float2 wv0 = ((const float2*)(Wres_s + i * 64))[l];
        float2 wv1 = ((const float2*)(Wres_s + (i + 1) * 64))[l];
#pragma unroll
        for (int m = 0; m < 4; m++) {
            float2 xv = *(const float2*)(f0_s + (w * 4 + m) * 64 + i);
            res[m].x += xv.x * wv0.x + xv.y * wv1.x;
            res[m].y += xv.x * wv0.y + xv.y * wv1.y;
        }
    }

    float2 hf[4];
    {
        float2 bv = ((const float2*)bf1_s)[l];
#pragma unroll
        for (int m = 0; m < 4; m++) hf[m] = bv;
    }
#pragma unroll 4
    for (int i = 0; i < 128; i += 2) {
        float2 wv0 = ((const float2*)(Wf1_s + i * 64))[l];
        float2 wv1 = ((const float2*)(Wf1_s + (i + 1) * 64))[l];
#pragma unroll
        for (int m = 0; m < 4; m++) {
            float2 xv = *(const float2*)(fin_s + (w * 4 + m) * 128 + i);
            hf[m].x += xv.x * wv0.x + xv.y * wv1.x;
            hf[m].y += xv.x * wv0.y + xv.y * wv1.y;
        }
    }

    float2 w2v = ((const float2*)Wf2_s)[l];
    float bf2v = bf2[0];
#pragma unroll
    for (int m = 0; m < 4; m++) {
        float hx = fmaxf(hf[m].x, 0.f), hy = fmaxf(hf[m].y, 0.f);
        float fw = wsum(hx * w2v.x + hy * w2v.y) + bf2v;
        fw = 1.f / (1.f + expf(-fw));
        float2 fu = make_float2(0.1f*fw*at[m].x + (1.f - fw)*mn[m].x + 0.8f*res[m].x,
                                0.1f*fw*at[m].y + (1.f - fw)*mn[m].y + 0.8f*res[m].y);
        ((float2*)(fu_s + (w * 4 + m) * 64))[l] = fu;
    }
    __syncwarp();

    float2 gg[4];
    {
        float2 bv = ((const float2*)b3_s)[l];
#pragma unroll
        for (int m = 0; m < 4; m++) gg[m] = bv;
    }
#pragma unroll 4
    for (int i = 0; i < 64; i += 2) {
        float2 wv0 = ((const float2*)(W3_s + i * 64))[l];
        float2 wv1 = ((const float2*)(W3_s + (i + 1) * 64))[l];
#pragma unroll
        for (int m = 0; m < 4; m++) {
            float2 xv = *(const float2*)(fu_s + (w * 4 + m) * 64 + i);
            gg[m].x += xv.x * wv0.x + xv.y * wv1.x;
            gg[m].y += xv.x * wv0.y + xv.y * wv1.y;
        }
    }

    float4 w4v = ((const float4*)W4_s)[l];
    float b40 = b4[0], b41 = b4[1];
#pragma unroll
    for (int m = 0; m < 4; m++) {
        float gx = fmaxf(gg[m].x, 0.f), gy = fmaxf(gg[m].y, 0.f);
        float o0 = wsum(gx * w4v.x + gy * w4v.z) + b40;
        float o1 = wsum(gx * w4v.y + gy * w4v.w) + b41;
        int n = blockIdx.x * 32 + w * 4 + m;
        if (l == 0 && n < Nn) ((float2*)out)[n] = make_float2(o0, o1);
    }
}

// ---------------- stream/event setup ----------------
static cudaStream_t g_sideStream = 0;
static cudaEvent_t  g_evFork = 0, g_evScan = 0, g_evJoin = 0;
namespace {
struct HxStreamInit {
    HxStreamInit() {
        if (cudaStreamCreateWithFlags(&g_sideStream, cudaStreamNonBlocking) != cudaSuccess)
            g_sideStream = 0;
        if (cudaEventCreateWithFlags(&g_evFork, cudaEventDisableTiming) != cudaSuccess)
            g_evFork = 0;
        if (cudaEventCreateWithFlags(&g_evScan, cudaEventDisableTiming) != cudaSuccess)
            g_evScan = 0;
        if (cudaEventCreateWithFlags(&g_evJoin, cudaEventDisableTiming) != cudaSuccess)
            g_evJoin = 0;
    }
};
static HxStreamInit g_hxStreamInit;
}

// ---------------- launch ----------------
extern "C" void kernel_launch(void* const* d_in, const int* in_sizes, int n_in,
                              void* d_out, int out_size) {
    const float* in_feat = (const float*)d_in[0];
    const int*   src     = (const int*)d_in[1];
    const int*   dst     = (const int*)d_in[2];
    const float* W1   = (const float*)d_in[3];
    const float* b1   = (const float*)d_in[4];
    const float* W2   = (const float*)d_in[5];
    const float* b2   = (const float*)d_in[6];
    const float* Wres = (const float*)d_in[7];
    const float* bres = (const float*)d_in[8];
    const float* Wattn= (const float*)d_in[9];
    const float* battn= (const float*)d_in[10];
    const float* Wf1  = (const float*)d_in[11];
    const float* bf1  = (const float*)d_in[12];
    const float* Wf2  = (const float*)d_in[13];
    const float* bf2  = (const float*)d_in[14];
    const float* W3   = (const float*)d_in[15];
    const float* b3   = (const float*)d_in[16];
    const float* W4   = (const float*)d_in[17];
    const float* b4   = (const float*)d_in[18];
    float* out = (float*)d_out;

    const int FC_SMEM  = FC_SMEM_FLOATS * 4;
    const int FIN_SMEM = FIN_SMEM_FLOATS * 4;
    cudaFuncSetAttribute((const void*)k_fc,
                         cudaFuncAttributeMaxDynamicSharedMemorySize, FC_SMEM);
    cudaFuncSetAttribute((const void*)k_final,
                         cudaFuncAttributeMaxDynamicSharedMemorySize, FIN_SMEM);

    const int FC_GRID = Nn / 16;
    bool par = (g_sideStream && g_evFork && g_evScan && g_evJoin);

    if (par) {
        cudaEventRecord(g_evFork, 0);
        cudaStreamWaitEvent(g_sideStream, g_evFork, 0);
        k_fc<<<FC_GRID, 256, FC_SMEM, g_sideStream>>>(in_feat, W1, b1, W2, b2);
        k_hist<<<(Ee / 4 + 255) / 256, 256>>>(dst);
        k_scan<<<NSCAN, 1024>>>();
        cudaEventRecord(g_evScan, 0);
        cudaStreamWaitEvent(g_sideStream, g_evScan, 0);
        k_make_s<<<(Nn * Hh / 4 + 255) / 256, 256, 0, g_sideStream>>>();
        k_scatter<<<(Ee / 4 + 255) / 256, 256>>>(src, dst);
        cudaEventRecord(g_evJoin, g_sideStream);
        cudaStreamWaitEvent(0, g_evJoin, 0);
    } else {
        k_hist<<<(Ee / 4 + 255) / 256, 256>>>(dst);
        k_scan<<<NSCAN, 1024>>>();
        k_scatter<<<(Ee / 4 + 255) / 256, 256>>>(src, dst);
        k_fc<<<FC_GRID, 256, FC_SMEM>>>(in_feat, W1, b1, W2, b2);
        k_make_s<<<(Nn * Hh / 4 + 255) / 256, 256>>>();
    }

    k_spmm<true><<<(Nn + 7) / 8, 256>>>();
    k_spmm<false><<<(Nn + 7) / 8, 256>>>();
    k_final<<<(Nn + 31) / 32, 256, FIN_SMEM>>>(Wres, bres, Wattn, battn,
                                               Wf1, bf1, Wf2, bf2,
                                               W3, b3, W4, b4, out);
}

// round 15
// speedup vs baseline: 1.4646x; 1.4646x over previous
#include <cuda_runtime.h>
#include <cuda_fp16.h>
#include <math.h>

#define Nn 50000
#define Ee 1600000
#define INF 128
#define Hh 64
#define NSCAN ((Nn + 1023) / 1024)   // 49

// ---------------- scratch ----------------
__device__ int    g_deg[Nn];          // zero-initialized; self-cleaned by k_scan_final
__device__ int    g_rowstart[Nn + 1];
__device__ int    g_cursor[Nn];
__device__ int    g_srcsorted[Ee];
__device__ int    g_blocksum[64];
__device__ float  g_dinv[Nn];
__device__ float  g_f0[Nn * Hh];
__device__ __half g_s[Nn * Hh];
__device__ float  g_f1[Nn * Hh];
__device__ __half g_s2[Nn * Hh];
__device__ float  g_f2[Nn * Hh];

__device__ __forceinline__ float wsum(float v) {
#pragma unroll
    for (int o = 16; o; o >>= 1) v += __shfl_xor_sync(0xffffffffu, v, o);
    return v;
}

// ---------------- CSR build ----------------
__global__ void k_hist(const int* __restrict__ dst) {
    int i = blockIdx.x * blockDim.x + threadIdx.x;
    if (i < Ee / 4) {
        int4 d = ((const int4*)dst)[i];
        atomicAdd(&g_deg[d.x], 1);
        atomicAdd(&g_deg[d.y], 1);
        atomicAdd(&g_deg[d.z], 1);
        atomicAdd(&g_deg[d.w], 1);
    }
}

__global__ void k_scan_partial() {
    __shared__ int wsh[32];
    int tid = threadIdx.x, lane = tid & 31, wid = tid >> 5;
    int i = blockIdx.x * 1024 + tid;
    int v = (i < Nn) ? g_deg[i] : 0;
    int x = v;
#pragma unroll
    for (int o = 1; o < 32; o <<= 1) {
        int t = __shfl_up_sync(0xffffffffu, x, o);
        if (lane >= o) x += t;
    }
    if (lane == 31) wsh[wid] = x;
    __syncthreads();
    if (wid == 0) {
        int y = wsh[lane];
#pragma unroll
        for (int o = 1; o < 32; o <<= 1) {
            int t = __shfl_up_sync(0xffffffffu, y, o);
            if (lane >= o) y += t;
        }
        wsh[lane] = y;
    }
    __syncthreads();
    int incl = x + (wid ? wsh[wid - 1] : 0);
    if (i < Nn) g_rowstart[i] = incl;
    if (tid == 1023) g_blocksum[blockIdx.x] = incl;
}

// merged scan-of-sums + finalize; also RE-ZEROES g_deg for the next invocation
__global__ void k_scan_final() {
    __shared__ int offsh;
    int tid = threadIdx.x;
    if (tid < 32) {
        int l = tid;
        int i0 = 2 * l, i1 = 2 * l + 1;
        int v0 = (i0 < NSCAN) ? g_blocksum[i0] : 0;
        int v1 = (i1 < NSCAN) ? g_blocksum[i1] : 0;
        int p = v0 + v1;
        int x = p;
#pragma unroll
        for (int o = 1; o < 32; o <<= 1) {
            int t = __shfl_up_sync(0xffffffffu, x, o);
            if (l >= o) x += t;
        }
        int excl = x - p;
        int b = blockIdx.x;
        if (i0 == b) offsh = excl;
        if (i1 == b) offsh = excl + v0;
        if (b == 0 && l == 31) g_rowstart[Nn] = x;
    }
    __syncthreads();
    int off = offsh;
    int i = blockIdx.x * 1024 + tid;
    if (i < Nn) {
        int incl = g_rowstart[i];
        int v = g_deg[i];
        g_deg[i] = 0;                      // self-clean for next call
        int excl = incl - v + off;
        g_rowstart[i] = excl;
        g_cursor[i] = excl;
        g_dinv[i] = rsqrtf((float)(v > 0 ? v : 1));
    }
}

__global__ void k_scatter(const int* __restrict__ src, const int* __restrict__ dst) {
    int i = blockIdx.x * blockDim.x + threadIdx.x;
    if (i < Ee / 4) {
        int4 s = ((const int4*)src)[i];
        int4 d = ((const int4*)dst)[i];
        g_srcsorted[atomicAdd(&g_cursor[d.x], 1)] = s.x;
        g_srcsorted[atomicAdd(&g_cursor[d.y], 1)] = s.y;
        g_srcsorted[atomicAdd(&g_cursor[d.z], 1)] = s.z;
        g_srcsorted[atomicAdd(&g_cursor[d.w], 1)] = s.w;
    }
}

// ---------------- f0 = relu(relu(X@W1+b1)@W2+b2)  (scalar FFMA) ----------
#define FC_SMEM_FLOATS (INF * Hh + Hh * Hh + Hh + Hh + 16 * INF + 16 * Hh)
__global__ void k_fc(const float* __restrict__ in_feat,
                     const float* __restrict__ W1, const float* __restrict__ b1,
                     const float* __restrict__ W2, const float* __restrict__ b2) {
    extern __shared__ float sm[];
    float* W1s = sm;
    float* W2s = W1s + INF * Hh;
    float* b1s = W2s + Hh * Hh;
    float* b2s = b1s + Hh;
    float* xsh = b2s + Hh;
    float* h1s = xsh + 16 * INF;

    int tid = threadIdx.x;
    for (int t = tid; t < 2048; t += 256) ((float4*)W1s)[t] = ((const float4*)W1)[t];
    for (int t = tid; t < 1024; t += 256) ((float4*)W2s)[t] = ((const float4*)W2)[t];
    if (tid < Hh) { b1s[tid] = b1[tid]; b2s[tid] = b2[tid]; }
    {
        const float4* xin = (const float4*)(in_feat + (long long)blockIdx.x * 16 * INF);
        for (int t = tid; t < 512; t += 256) ((float4*)xsh)[t] = xin[t];
    }
    __syncthreads();

    int j = tid & 63, g = tid >> 6;
    float a0 = b1s[j], a1 = a0, a2 = a0, a3 = a0;
#pragma unroll 8
    for (int i = 0; i < INF; i += 2) {
        float w0 = W1s[i * Hh + j];
        float w1 = W1s[(i + 1) * Hh + j];
        float2 x0 = *(const float2*)(xsh + (4 * g + 0) * INF + i);
        float2 x1 = *(const float2*)(xsh + (4 * g + 1) * INF + i);
        float2 x2 = *(const float2*)(xsh + (4 * g + 2) * INF + i);
        float2 x3 = *(const float2*)(xsh + (4 * g + 3) * INF + i);
        a0 += x0.x * w0 + x0.y * w1;
        a1 += x1.x * w0 + x1.y * w1;
        a2 += x2.x * w0 + x2.y * w1;
        a3 += x3.x * w0 + x3.y * w1;
    }
    h1s[(4 * g + 0) * Hh + j] = fmaxf(a0, 0.f);
    h1s[(4 * g + 1) * Hh + j] = fmaxf(a1, 0.f);
    h1s[(4 * g + 2) * Hh + j] = fmaxf(a2, 0.f);
    h1s[(4 * g + 3) * Hh + j] = fmaxf(a3, 0.f);
    __syncthreads();

    float c0 = b2s[j], c1 = c0, c2 = c0, c3 = c0;
#pragma unroll 8
    for (int i = 0; i < Hh; i += 2) {
        float w0 = W2s[i * Hh + j];
        float w1 = W2s[(i + 1) * Hh + j];
        float2 x0 = *(const float2*)(h1s + (4 * g + 0) * Hh + i);
        float2 x1 = *(const float2*)(h1s + (4 * g + 1) * Hh + i);
        float2 x2 = *(const float2*)(h1s + (4 * g + 2) * Hh + i);
        float2 x3 = *(const float2*)(h1s + (4 * g + 3) * Hh + i);
        c0 += x0.x * w0 + x0.y * w1;
        c1 += x1.x * w0 + x1.y * w1;
        c2 += x2.x * w0 + x2.y * w1;
        c3 += x3.x * w0 + x3.y * w1;
    }
    c0 = fmaxf(c0, 0.f); c1 = fmaxf(c1, 0.f);
    c2 = fmaxf(c2, 0.f); c3 = fmaxf(c3, 0.f);
    int n0 = blockIdx.x * 16 + 4 * g;
    g_f0[(n0 + 0) * Hh + j] = c0;
    g_f0[(n0 + 1) * Hh + j] = c1;
    g_f0[(n0 + 2) * Hh + j] = c2;
    g_f0[(n0 + 3) * Hh + j] = c3;
}

// ---------------- s = fp16(f0 * dinv) ----------------
__global__ void k_make_s() {
    int i = blockIdx.x * blockDim.x + threadIdx.x;
    if (i < Nn * Hh / 4) {
        float4 v = ((const float4*)g_f0)[i];
        float dv = g_dinv[i >> 4];
        __half2* Sh = (__half2*)g_s;
        Sh[2 * i]     = __floats2half2_rn(v.x * dv, v.y * dv);
        Sh[2 * i + 1] = __floats2half2_rn(v.z * dv, v.w * dv);
    }
}

// ---------------- SpMM (R9): fOut = base - dinv * (A @ sIn), fp16 gather, 8-wide ----
template <bool WRITE_S>
__global__ void k_spmm() {
    int w = threadIdx.x >> 5;
    int row = blockIdx.x * 8 + w;
    if (row >= Nn) return;
    int lane = threadIdx.x & 31;
    const __half2* S = WRITE_S ? (const __half2*)g_s : (const __half2*)g_s2;
    const float2*  B = WRITE_S ? (const float2*)g_f0 : (const float2*)g_f1;
    float2* FO = WRITE_S ? (float2*)g_f1 : (float2*)g_f2;

    int beg = __ldg(&g_rowstart[row]), end = __ldg(&g_rowstart[row + 1]);
    float ax = 0.f, ay = 0.f, bx = 0.f, by = 0.f;
    float cx = 0.f, cy = 0.f, dx = 0.f, dy = 0.f;
    int k = beg;
    for (; k + 7 < end; k += 8) {
        int s0 = __ldg(&g_srcsorted[k]);
        int s1 = __ldg(&g_srcsorted[k + 1]);
        int s2 = __ldg(&g_srcsorted[k + 2]);
        int s3 = __ldg(&g_srcsorted[k + 3]);
        int s4 = __ldg(&g_srcsorted[k + 4]);
        int s5 = __ldg(&g_srcsorted[k + 5]);
        int s6 = __ldg(&g_srcsorted[k + 6]);
        int s7 = __ldg(&g_srcsorted[k + 7]);
        float2 v0 = __half22float2(__ldg(&S[s0 * 32 + lane]));
        float2 v1 = __half22float2(__ldg(&S[s1 * 32 + lane]));
        float2 v2 = __half22float2(__ldg(&S[s2 * 32 + lane]));
        float2 v3 = __half22float2(__ldg(&S[s3 * 32 + lane]));
        float2 v4 = __half22float2(__ldg(&S[s4 * 32 + lane]));
        float2 v5 = __half22float2(__ldg(&S[s5 * 32 + lane]));
        float2 v6 = __half22float2(__ldg(&S[s6 * 32 + lane]));
        float2 v7 = __half22float2(__ldg(&S[s7 * 32 + lane]));
        ax += v0.x + v4.x; ay += v0.y + v4.y;
        bx += v1.x + v5.x; by += v1.y + v5.y;
        cx += v2.x + v6.x; cy += v2.y + v6.y;
        dx += v3.x + v7.x; dy += v3.y + v7.y;
    }
    for (; k + 1 < end; k += 2) {
        int s0 = __ldg(&g_srcsorted[k]);
        int s1 = __ldg(&g_srcsorted[k + 1]);
        float2 v0 = __half22float2(__ldg(&S[s0 * 32 + lane]));
        float2 v1 = __half22float2(__ldg(&S[s1 * 32 + lane]));
        ax += v0.x; ay += v0.y;
        bx += v1.x; by += v1.y;
    }
    if (k < end) {
        int s0 = __ldg(&g_srcsorted[k]);
        float2 v0 = __half22float2(__ldg(&S[s0 * 32 + lane]));
        ax += v0.x; ay += v0.y;
    }
    ax += bx + cx + dx;
    ay += by + cy + dy;
    float dv = g_dinv[row];
    float2 bv = B[row * 32 + lane];
    float2 f = make_float2(bv.x - dv * ax, bv.y - dv * ay);
    FO[row * 32 + lane] = f;
    if (WRITE_S) {
        ((__half2*)g_s2)[row * 32 + lane] = __floats2half2_rn(f.x * dv, f.y * dv);
    }
}

// ---------------- fusion + heads ----------------
#define FIN_SMEM_FLOATS (4096 + 8192 + 4096 + 64 + 64 + 128 + 64 + 64 + 64 + 32*128 + 32*64 + 32*64)
__global__ void k_final(const float* __restrict__ Wres, const float* __restrict__ bres,
                        const float* __restrict__ Wattn, const float* __restrict__ battn,
                        const float* __restrict__ Wf1, const float* __restrict__ bf1,
                        const float* __restrict__ Wf2, const float* __restrict__ bf2,
                        const float* __restrict__ W3, const float* __restrict__ b3,
                        const float* __restrict__ W4, const float* __restrict__ b4,
                        float* __restrict__ out) {
    extern __shared__ float sm[];
    float* Wres_s  = sm;
    float* Wf1_s   = Wres_s + 4096;
    float* W3_s    = Wf1_s + 8192;
    float* Wattn_s = W3_s + 4096;
    float* Wf2_s   = Wattn_s + 64;
    float* W4_s    = Wf2_s + 64;
    float* bres_s  = W4_s + 128;
    float* bf1_s   = bres_s + 64;
    float* b3_s    = bf1_s + 64;
    float* fin_s   = b3_s + 64;
    float* f0_s    = fin_s + 32 * 128;
    float* fu_s    = f0_s + 32 * 64;

    int tid = threadIdx.x;
    for (int t = tid; t < 1024; t += 256) ((float4*)Wres_s)[t] = ((const float4*)Wres)[t];
    for (int t = tid; t < 2048; t += 256) ((float4*)Wf1_s)[t] = ((const float4*)Wf1)[t];
    for (int t = tid; t < 1024; t += 256) ((float4*)W3_s)[t] = ((const float4*)W3)[t];
    if (tid < 64) {
        Wattn_s[tid] = Wattn[tid]; Wf2_s[tid] = Wf2[tid];
        bres_s[tid] = bres[tid];   bf1_s[tid] = bf1[tid]; b3_s[tid] = b3[tid];
    }
    if (tid < 128) W4_s[tid] = W4[tid];
    __syncthreads();

    int w = tid >> 5, l = tid & 31;

    float2 at[4], mn[4];
    const float2* F0 = (const float2*)g_f0;
    const float2* F1 = (const float2*)g_f1;
    const float2* F2 = (const float2*)g_f2;
    float2 wat = ((const float2*)Wattn_s)[l];
    float bat = battn[0];

#pragma unroll
    for (int m = 0; m < 4; m++) {
        int ln = w * 4 + m;
        int n = blockIdx.x * 32 + ln;
        int nc = (n < Nn) ? n : (Nn - 1);
        float2 f0 = F0[nc * 32 + l];
        float2 f1 = F1[nc * 32 + l];
        float2 f2 = F2[nc * 32 + l];
        ((float2*)(f0_s + ln * 64))[l] = f0;

        float2 c0 = make_float2(3.f*f0.x - 3.f*f1.x + 0.75f*f2.x,
                                3.f*f0.y - 3.f*f1.y + 0.75f*f2.y);
        float2 c1 = make_float2(3.f*f1.x - 1.5f*f2.x, 3.f*f1.y - 1.5f*f2.y);
        float2 c2 = make_float2(0.75f*f2.x, 0.75f*f2.y);

        float s0 = wsum(c0.x*wat.x + c0.y*wat.y) + bat;
        float s1 = wsum(c1.x*wat.x + c1.y*wat.y) + bat;
        float s2 = wsum(c2.x*wat.x + c2.y*wat.y) + bat;
        float mx = fmaxf(s0, fmaxf(s1, s2));
        float e0 = expf(s0 - mx), e1 = expf(s1 - mx), e2 = expf(s2 - mx);
        float inv = 1.f / (e0 + e1 + e2);
        float w0 = e0*inv, w1 = e1*inv, w2 = e2*inv;

        at[m] = make_float2(w0*c0.x + w1*c1.x + w2*c2.x,
                            w0*c0.y + w1*c1.y + w2*c2.y);
        const float third = 1.f / 3.f;
        mn[m] = make_float2((c0.x + c1.x + c2.x)*third, (c0.y + c1.y + c2.y)*third);

        float* fin = fin_s + ln * 128;
        ((float2*)fin)[l] = at[m];
        ((float2*)(fin + 64))[l] = mn[m];
    }
    __syncwarp();

    float2 res[4];
    {
        float2 bv = ((const float2*)bres_s)[l];
#pragma unroll
        for (int m = 0; m < 4; m++) res[m] = bv;
    }
#pragma unroll 4
    for (int i = 0; i < 64; i += 2) {
        float2 wv0 = ((const float2*)(Wres_s + i * 64))[l];
        float2 wv1 = ((const float2*)(Wres_s + (i + 1) * 64))[l];
#pragma unroll
        for (int m = 0; m < 4; m++) {
            float2 xv = *(const float2*)(f0_s + (w * 4 + m) * 64 + i);
            res[m].x += xv.x * wv0.x + xv.y * wv1.x;
            res[m].y += xv.x * wv0.y + xv.y * wv1.y;
        }
    }

    float2 hf[4];
    {
        float2 bv = ((const float2*)bf1_s)[l];
#pragma unroll
        for (int m = 0; m < 4; m++) hf[m] = bv;
    }
#pragma unroll 4
    for (int i = 0; i < 128; i += 2) {
        float2 wv0 = ((const float2*)(Wf1_s + i * 64))[l];
        float2 wv1 = ((const float2*)(Wf1_s + (i + 1) * 64))[l];
#pragma unroll
        for (int m = 0; m < 4; m++) {
            float2 xv = *(const float2*)(fin_s + (w * 4 + m) * 128 + i);
            hf[m].x += xv.x * wv0.x + xv.y * wv1.x;
            hf[m].y += xv.x * wv0.y + xv.y * wv1.y;
        }
    }

    float2 w2v = ((const float2*)Wf2_s)[l];
    float bf2v = bf2[0];
#pragma unroll
    for (int m = 0; m < 4; m++) {
        float hx = fmaxf(hf[m].x, 0.f), hy = fmaxf(hf[m].y, 0.f);
        float fw = wsum(hx * w2v.x + hy * w2v.y) + bf2v;
        fw = 1.f / (1.f + expf(-fw));
        float2 fu = make_float2(0.1f*fw*at[m].x + (1.f - fw)*mn[m].x + 0.8f*res[m].x,
                                0.1f*fw*at[m].y + (1.f - fw)*mn[m].y + 0.8f*res[m].y);
        ((float2*)(fu_s + (w * 4 + m) * 64))[l] = fu;
    }
    __syncwarp();

    float2 gg[4];
    {
        float2 bv = ((const float2*)b3_s)[l];
#pragma unroll
        for (int m = 0; m < 4; m++) gg[m] = bv;
    }
#pragma unroll 4
    for (int i = 0; i < 64; i += 2) {
        float2 wv0 = ((const float2*)(W3_s + i * 64))[l];
        float2 wv1 = ((const float2*)(W3_s + (i + 1) * 64))[l];
#pragma unroll
        for (int m = 0; m < 4; m++) {
            float2 xv = *(const float2*)(fu_s + (w * 4 + m) * 64 + i);
            gg[m].x += xv.x * wv0.x + xv.y * wv1.x;
            gg[m].y += xv.x * wv0.y + xv.y * wv1.y;
        }
    }

    float4 w4v = ((const float4*)W4_s)[l];
    float b40 = b4[0], b41 = b4[1];
#pragma unroll
    for (int m = 0; m < 4; m++) {
        float gx = fmaxf(gg[m].x, 0.f), gy = fmaxf(gg[m].y, 0.f);
        float o0 = wsum(gx * w4v.x + gy * w4v.z) + b40;
        float o1 = wsum(gx * w4v.y + gy * w4v.w) + b41;
        int n = blockIdx.x * 32 + w * 4 + m;
        if (l == 0 && n < Nn) ((float2*)out)[n] = make_float2(o0, o1);
    }
}

// ---------------- stream/event setup ----------------
static cudaStream_t g_sideStream = 0;
static cudaEvent_t  g_evFork = 0, g_evScan = 0, g_evJoin = 0;
namespace {
struct HxStreamInit {
    HxStreamInit() {
        if (cudaStreamCreateWithFlags(&g_sideStream, cudaStreamNonBlocking) != cudaSuccess)
            g_sideStream = 0;
        if (cudaEventCreateWithFlags(&g_evFork, cudaEventDisableTiming) != cudaSuccess)
            g_evFork = 0;
        if (cudaEventCreateWithFlags(&g_evScan, cudaEventDisableTiming) != cudaSuccess)
            g_evScan = 0;
        if (cudaEventCreateWithFlags(&g_evJoin, cudaEventDisableTiming) != cudaSuccess)
            g_evJoin = 0;
    }
};
static HxStreamInit g_hxStreamInit;
}

// ---------------- launch ----------------
extern "C" void kernel_launch(void* const* d_in, const int* in_sizes, int n_in,
                              void* d_out, int out_size) {
    const float* in_feat = (const float*)d_in[0];
    const int*   src     = (const int*)d_in[1];
    const int*   dst     = (const int*)d_in[2];
    const float* W1   = (const float*)d_in[3];
    const float* b1   = (const float*)d_in[4];
    const float* W2   = (const float*)d_in[5];
    const float* b2   = (const float*)d_in[6];
    const float* Wres = (const float*)d_in[7];
    const float* bres = (const float*)d_in[8];
    const float* Wattn= (const float*)d_in[9];
    const float* battn= (const float*)d_in[10];
    const float* Wf1  = (const float*)d_in[11];
    const float* bf1  = (const float*)d_in[12];
    const float* Wf2  = (const float*)d_in[13];
    const float* bf2  = (const float*)d_in[14];
    const float* W3   = (const float*)d_in[15];
    const float* b3   = (const float*)d_in[16];
    const float* W4   = (const float*)d_in[17];
    const float* b4   = (const float*)d_in[18];
    float* out = (float*)d_out;

    const int FC_SMEM  = FC_SMEM_FLOATS * 4;
    const int FIN_SMEM = FIN_SMEM_FLOATS * 4;
    cudaFuncSetAttribute((const void*)k_fc,
                         cudaFuncAttributeMaxDynamicSharedMemorySize, FC_SMEM);
    cudaFuncSetAttribute((const void*)k_final,
                         cudaFuncAttributeMaxDynamicSharedMemorySize, FIN_SMEM);

    const int FC_GRID = Nn / 16;
    bool par = (g_sideStream && g_evFork && g_evScan && g_evJoin);

    if (par) {
        cudaEventRecord(g_evFork, 0);
        cudaStreamWaitEvent(g_sideStream, g_evFork, 0);
        k_fc<<<FC_GRID, 256, FC_SMEM, g_sideStream>>>(in_feat, W1, b1, W2, b2);
        k_hist<<<(Ee / 4 + 255) / 256, 256>>>(dst);
        k_scan_partial<<<NSCAN, 1024>>>();
        k_scan_final<<<NSCAN, 1024>>>();
        cudaEventRecord(g_evScan, 0);
        cudaStreamWaitEvent(g_sideStream, g_evScan, 0);
        k_make_s<<<(Nn * Hh / 4 + 255) / 256, 256, 0, g_sideStream>>>();
        k_scatter<<<(Ee / 4 + 255) / 256, 256>>>(src, dst);
        cudaEventRecord(g_evJoin, g_sideStream);
        cudaStreamWaitEvent(0, g_evJoin, 0);
    } else {
        k_hist<<<(Ee / 4 + 255) / 256, 256>>>(dst);
        k_scan_partial<<<NSCAN, 1024>>>();
        k_scan_final<<<NSCAN, 1024>>>();
        k_scatter<<<(Ee / 4 + 255) / 256, 256>>>(src, dst);
        k_fc<<<FC_GRID, 256, FC_SMEM>>>(in_feat, W1, b1, W2, b2);
        k_make_s<<<(Nn * Hh / 4 + 255) / 256, 256>>>();
    }

    k_spmm<true><<<(Nn + 7) / 8, 256>>>();
    k_spmm<false><<<(Nn + 7) / 8, 256>>>();
    k_final<<<(Nn + 31) / 32, 256, FIN_SMEM>>>(Wres, bres, Wattn, battn,
                                               Wf1, bf1, Wf2, bf2,
                                               W3, b3, W4, b4, out);
}

// round 16
// speedup vs baseline: 1.4914x; 1.0183x over previous
#include <cuda_runtime.h>
#include <cuda_fp16.h>
#include <math.h>

#define Nn 50000
#define Ee 1600000
#define INF 128
#define Hh 64
#define NSCAN ((Nn + 1023) / 1024)   // 49

// ---------------- scratch ----------------
__device__ int    g_deg[Nn];          // zero-initialized; self-cleaned by k_scan_final
__device__ int    g_rowstart[Nn + 1];
__device__ int    g_cursor[Nn];
__device__ int    g_srcsorted[Ee];
__device__ int    g_blocksum[64];
__device__ float  g_dinv[Nn];
__device__ float  g_f0[Nn * Hh];
__device__ __half g_s[Nn * Hh];
__device__ float  g_f1[Nn * Hh];
__device__ __half g_s2[Nn * Hh];
__device__ float  g_f2[Nn * Hh];

__device__ __forceinline__ float wsum(float v) {
#pragma unroll
    for (int o = 16; o; o >>= 1) v += __shfl_xor_sync(0xffffffffu, v, o);
    return v;
}

// ---------------- CSR build ----------------
__global__ void k_hist(const int* __restrict__ dst) {
    int i = blockIdx.x * blockDim.x + threadIdx.x;
    if (i < Ee / 4) {
        int4 d = ((const int4*)dst)[i];
        atomicAdd(&g_deg[d.x], 1);
        atomicAdd(&g_deg[d.y], 1);
        atomicAdd(&g_deg[d.z], 1);
        atomicAdd(&g_deg[d.w], 1);
    }
}

__global__ void k_scan_partial() {
    __shared__ int wsh[32];
    int tid = threadIdx.x, lane = tid & 31, wid = tid >> 5;
    int i = blockIdx.x * 1024 + tid;
    int v = (i < Nn) ? g_deg[i] : 0;
    int x = v;
#pragma unroll
    for (int o = 1; o < 32; o <<= 1) {
        int t = __shfl_up_sync(0xffffffffu, x, o);
        if (lane >= o) x += t;
    }
    if (lane == 31) wsh[wid] = x;
    __syncthreads();
    if (wid == 0) {
        int y = wsh[lane];
#pragma unroll
        for (int o = 1; o < 32; o <<= 1) {
            int t = __shfl_up_sync(0xffffffffu, y, o);
            if (lane >= o) y += t;
        }
        wsh[lane] = y;
    }
    __syncthreads();
    int incl = x + (wid ? wsh[wid - 1] : 0);
    if (i < Nn) g_rowstart[i] = incl;
    if (tid == 1023) g_blocksum[blockIdx.x] = incl;
}

// finalize, vectorized: 4 nodes/thread via int4/float4; also re-zeroes g_deg.
// grid = ceil(Nn/4096) = 13 blocks of 1024 threads (Nn divisible by 4).
__global__ void k_scan_final() {
    __shared__ int offsh[64];
    int tid = threadIdx.x;
    if (tid < 32) {
        int l = tid;
        int i0 = 2 * l, i1 = 2 * l + 1;
        int v0 = (i0 < NSCAN) ? g_blocksum[i0] : 0;
        int v1 = (i1 < NSCAN) ? g_blocksum[i1] : 0;
        int p = v0 + v1;
        int x = p;
#pragma unroll
        for (int o = 1; o < 32; o <<= 1) {
            int t = __shfl_up_sync(0xffffffffu, x, o);
            if (l >= o) x += t;
        }
        int excl = x - p;
        offsh[i0] = excl;
        offsh[i1] = excl + v0;
        if (blockIdx.x == 0 && l == 31) g_rowstart[Nn] = x;  // grand total
    }
    __syncthreads();
    int i4 = (blockIdx.x * 1024 + tid) * 4;
    if (i4 < Nn) {
        int4 incl4 = *(const int4*)&g_rowstart[i4];
        int4 v4    = *(const int4*)&g_deg[i4];
        int off = offsh[i4 >> 10];
        int4 ex;
        ex.x = off + incl4.x - v4.x;
        ex.y = off + incl4.y - v4.y;
        ex.z = off + incl4.z - v4.z;
        ex.w = off + incl4.w - v4.w;
        *(int4*)&g_rowstart[i4] = ex;
        *(int4*)&g_cursor[i4]   = ex;
        float4 dv;
        dv.x = rsqrtf((float)(v4.x > 0 ? v4.x : 1));
        dv.y = rsqrtf((float)(v4.y > 0 ? v4.y : 1));
        dv.z = rsqrtf((float)(v4.z > 0 ? v4.z : 1));
        dv.w = rsqrtf((float)(v4.w > 0 ? v4.w : 1));
        *(float4*)&g_dinv[i4] = dv;
        *(int4*)&g_deg[i4] = make_int4(0, 0, 0, 0);   // self-clean for next call
    }
}

__global__ void k_scatter(const int* __restrict__ src, const int* __restrict__ dst) {
    int i = blockIdx.x * blockDim.x + threadIdx.x;
    if (i < Ee / 4) {
        int4 s = ((const int4*)src)[i];
        int4 d = ((const int4*)dst)[i];
        g_srcsorted[atomicAdd(&g_cursor[d.x], 1)] = s.x;
        g_srcsorted[atomicAdd(&g_cursor[d.y], 1)] = s.y;
        g_srcsorted[atomicAdd(&g_cursor[d.z], 1)] = s.z;
        g_srcsorted[atomicAdd(&g_cursor[d.w], 1)] = s.w;
    }
}

// ---------------- f0 = relu(relu(X@W1+b1)@W2+b2)  (scalar FFMA) ----------
#define FC_SMEM_FLOATS (INF * Hh + Hh * Hh + Hh + Hh + 16 * INF + 16 * Hh)
__global__ void k_fc(const float* __restrict__ in_feat,
                     const float* __restrict__ W1, const float* __restrict__ b1,
                     const float* __restrict__ W2, const float* __restrict__ b2) {
    extern __shared__ float sm[];
    float* W1s = sm;
    float* W2s = W1s + INF * Hh;
    float* b1s = W2s + Hh * Hh;
    float* b2s = b1s + Hh;
    float* xsh = b2s + Hh;
    float* h1s = xsh + 16 * INF;

    int tid = threadIdx.x;
    for (int t = tid; t < 2048; t += 256) ((float4*)W1s)[t] = ((const float4*)W1)[t];
    for (int t = tid; t < 1024; t += 256) ((float4*)W2s)[t] = ((const float4*)W2)[t];
    if (tid < Hh) { b1s[tid] = b1[tid]; b2s[tid] = b2[tid]; }
    {
        const float4* xin = (const float4*)(in_feat + (long long)blockIdx.x * 16 * INF);
        for (int t = tid; t < 512; t += 256) ((float4*)xsh)[t] = xin[t];
    }
    __syncthreads();

    int j = tid & 63, g = tid >> 6;
    float a0 = b1s[j], a1 = a0, a2 = a0, a3 = a0;
#pragma unroll 8
    for (int i = 0; i < INF; i += 2) {
        float w0 = W1s[i * Hh + j];
        float w1 = W1s[(i + 1) * Hh + j];
        float2 x0 = *(const float2*)(xsh + (4 * g + 0) * INF + i);
        float2 x1 = *(const float2*)(xsh + (4 * g + 1) * INF + i);
        float2 x2 = *(const float2*)(xsh + (4 * g + 2) * INF + i);
        float2 x3 = *(const float2*)(xsh + (4 * g + 3) * INF + i);
        a0 += x0.x * w0 + x0.y * w1;
        a1 += x1.x * w0 + x1.y * w1;
        a2 += x2.x * w0 + x2.y * w1;
        a3 += x3.x * w0 + x3.y * w1;
    }
    h1s[(4 * g + 0) * Hh + j] = fmaxf(a0, 0.f);
    h1s[(4 * g + 1) * Hh + j] = fmaxf(a1, 0.f);
    h1s[(4 * g + 2) * Hh + j] = fmaxf(a2, 0.f);
    h1s[(4 * g + 3) * Hh + j] = fmaxf(a3, 0.f);
    __syncthreads();

    float c0 = b2s[j], c1 = c0, c2 = c0, c3 = c0;
#pragma unroll 8
    for (int i = 0; i < Hh; i += 2) {
        float w0 = W2s[i * Hh + j];
        float w1 = W2s[(i + 1) * Hh + j];
        float2 x0 = *(const float2*)(h1s + (4 * g + 0) * Hh + i);
        float2 x1 = *(const float2*)(h1s + (4 * g + 1) * Hh + i);
        float2 x2 = *(const float2*)(h1s + (4 * g + 2) * Hh + i);
        float2 x3 = *(const float2*)(h1s + (4 * g + 3) * Hh + i);
        c0 += x0.x * w0 + x0.y * w1;
        c1 += x1.x * w0 + x1.y * w1;
        c2 += x2.x * w0 + x2.y * w1;
        c3 += x3.x * w0 + x3.y * w1;
    }
    c0 = fmaxf(c0, 0.f); c1 = fmaxf(c1, 0.f);
    c2 = fmaxf(c2, 0.f); c3 = fmaxf(c3, 0.f);
    int n0 = blockIdx.x * 16 + 4 * g;
    g_f0[(n0 + 0) * Hh + j] = c0;
    g_f0[(n0 + 1) * Hh + j] = c1;
    g_f0[(n0 + 2) * Hh + j] = c2;
    g_f0[(n0 + 3) * Hh + j] = c3;
}

// ---------------- s = fp16(f0 * dinv) ----------------
__global__ void k_make_s() {
    int i = blockIdx.x * blockDim.x + threadIdx.x;
    if (i < Nn * Hh / 4) {
        float4 v = ((const float4*)g_f0)[i];
        float dv = g_dinv[i >> 4];
        __half2* Sh = (__half2*)g_s;
        Sh[2 * i]     = __floats2half2_rn(v.x * dv, v.y * dv);
        Sh[2 * i + 1] = __floats2half2_rn(v.z * dv, v.w * dv);
    }
}

// ---------------- SpMM (R9): fOut = base - dinv * (A @ sIn), fp16 gather, 8-wide ----
template <bool WRITE_S>
__global__ void k_spmm() {
    int w = threadIdx.x >> 5;
    int row = blockIdx.x * 8 + w;
    if (row >= Nn) return;
    int lane = threadIdx.x & 31;
    const __half2* S = WRITE_S ? (const __half2*)g_s : (const __half2*)g_s2;
    const float2*  B = WRITE_S ? (const float2*)g_f0 : (const float2*)g_f1;
    float2* FO = WRITE_S ? (float2*)g_f1 : (float2*)g_f2;

    int beg = __ldg(&g_rowstart[row]), end = __ldg(&g_rowstart[row + 1]);
    float ax = 0.f, ay = 0.f, bx = 0.f, by = 0.f;
    float cx = 0.f, cy = 0.f, dx = 0.f, dy = 0.f;
    int k = beg;
    for (; k + 7 < end; k += 8) {
        int s0 = __ldg(&g_srcsorted[k]);
        int s1 = __ldg(&g_srcsorted[k + 1]);
        int s2 = __ldg(&g_srcsorted[k + 2]);
        int s3 = __ldg(&g_srcsorted[k + 3]);
        int s4 = __ldg(&g_srcsorted[k + 4]);
        int s5 = __ldg(&g_srcsorted[k + 5]);
        int s6 = __ldg(&g_srcsorted[k + 6]);
        int s7 = __ldg(&g_srcsorted[k + 7]);
        float2 v0 = __half22float2(__ldg(&S[s0 * 32 + lane]));
        float2 v1 = __half22float2(__ldg(&S[s1 * 32 + lane]));
        float2 v2 = __half22float2(__ldg(&S[s2 * 32 + lane]));
        float2 v3 = __half22float2(__ldg(&S[s3 * 32 + lane]));
        float2 v4 = __half22float2(__ldg(&S[s4 * 32 + lane]));
        float2 v5 = __half22float2(__ldg(&S[s5 * 32 + lane]));
        float2 v6 = __half22float2(__ldg(&S[s6 * 32 + lane]));
        float2 v7 = __half22float2(__ldg(&S[s7 * 32 + lane]));
        ax += v0.x + v4.x; ay += v0.y + v4.y;
        bx += v1.x + v5.x; by += v1.y + v5.y;
        cx += v2.x + v6.x; cy += v2.y + v6.y;
        dx += v3.x + v7.x; dy += v3.y + v7.y;
    }
    for (; k + 1 < end; k += 2) {
        int s0 = __ldg(&g_srcsorted[k]);
        int s1 = __ldg(&g_srcsorted[k + 1]);
        float2 v0 = __half22float2(__ldg(&S[s0 * 32 + lane]));
        float2 v1 = __half22float2(__ldg(&S[s1 * 32 + lane]));
        ax += v0.x; ay += v0.y;
        bx += v1.x; by += v1.y;
    }
    if (k < end) {
        int s0 = __ldg(&g_srcsorted[k]);
        float2 v0 = __half22float2(__ldg(&S[s0 * 32 + lane]));
        ax += v0.x; ay += v0.y;
    }
    ax += bx + cx + dx;
    ay += by + cy + dy;
    float dv = g_dinv[row];
    float2 bv = B[row * 32 + lane];
    float2 f = make_float2(bv.x - dv * ax, bv.y - dv * ay);
    FO[row * 32 + lane] = f;
    if (WRITE_S) {
        ((__half2*)g_s2)[row * 32 + lane] = __floats2half2_rn(f.x * dv, f.y * dv);
    }
}

// ---------------- fusion + heads ----------------
#define FIN_SMEM_FLOATS (4096 + 8192 + 4096 + 64 + 64 + 128 + 64 + 64 + 64 + 32*128 + 32*64 + 32*64)
__global__ void k_final(const float* __restrict__ Wres, const float* __restrict__ bres,
                        const float* __restrict__ Wattn, const float* __restrict__ battn,
                        const float* __restrict__ Wf1, const float* __restrict__ bf1,
                        const float* __restrict__ Wf2, const float* __restrict__ bf2,
                        const float* __restrict__ W3, const float* __restrict__ b3,
                        const float* __restrict__ W4, const float* __restrict__ b4,
                        float* __restrict__ out) {
    extern __shared__ float sm[];
    float* Wres_s  = sm;
    float* Wf1_s   = Wres_s + 4096;
    float* W3_s    = Wf1_s + 8192;
    float* Wattn_s = W3_s + 4096;
    float* Wf2_s   = Wattn_s + 64;
    float* W4_s    = Wf2_s + 64;
    float* bres_s  = W4_s + 128;
    float* bf1_s   = bres_s + 64;
    float* b3_s    = bf1_s + 64;
    float* fin_s   = b3_s + 64;
    float* f0_s    = fin_s + 32 * 128;
    float* fu_s    = f0_s + 32 * 64;

    int tid = threadIdx.x;
    for (int t = tid; t < 1024; t += 256) ((float4*)Wres_s)[t] = ((const float4*)Wres)[t];
    for (int t = tid; t < 2048; t += 256) ((float4*)Wf1_s)[t] = ((const float4*)Wf1)[t];
    for (int t = tid; t < 1024; t += 256) ((float4*)W3_s)[t] = ((const float4*)W3)[t];
    if (tid < 64) {
        Wattn_s[tid] = Wattn[tid]; Wf2_s[tid] = Wf2[tid];
        bres_s[tid] = bres[tid];   bf1_s[tid] = bf1[tid]; b3_s[tid] = b3[tid];
    }
    if (tid < 128) W4_s[tid] = W4[tid];
    __syncthreads();

    int w = tid >> 5, l = tid & 31;

    float2 at[4], mn[4];
    const float2* F0 = (const float2*)g_f0;
    const float2* F1 = (const float2*)g_f1;
    const float2* F2 = (const float2*)g_f2;
    float2 wat = ((const float2*)Wattn_s)[l];
    float bat = battn[0];

#pragma unroll
    for (int m = 0; m < 4; m++) {
        int ln = w * 4 + m;
        int n = blockIdx.x * 32 + ln;
        int nc = (n < Nn) ? n : (Nn - 1);
        float2 f0 = F0[nc * 32 + l];
        float2 f1 = F1[nc * 32 + l];
        float2 f2 = F2[nc * 32 + l];
        ((float2*)(f0_s + ln * 64))[l] = f0;

        float2 c0 = make_float2(3.f*f0.x - 3.f*f1.x + 0.75f*f2.x,
                                3.f*f0.y - 3.f*f1.y + 0.75f*f2.y);
        float2 c1 = make_float2(3.f*f1.x - 1.5f*f2.x, 3.f*f1.y - 1.5f*f2.y);
        float2 c2 = make_float2(0.75f*f2.x, 0.75f*f2.y);

        float s0 = wsum(c0.x*wat.x + c0.y*wat.y) + bat;
        float s1 = wsum(c1.x*wat.x + c1.y*wat.y) + bat;
        float s2 = wsum(c2.x*wat.x + c2.y*wat.y) + bat;
        float mx = fmaxf(s0, fmaxf(s1, s2));
        float e0 = expf(s0 - mx), e1 = expf(s1 - mx), e2 = expf(s2 - mx);
        float inv = 1.f / (e0 + e1 + e2);
        float w0 = e0*inv, w1 = e1*inv, w2 = e2*inv;

        at[m] = make_float2(w0*c0.x + w1*c1.x + w2*c2.x,
                            w0*c0.y + w1*c1.y + w2*c2.y);
        const float third = 1.f / 3.f;
        mn[m] = make_float2((c0.x + c1.x + c2.x)*third, (c0.y + c1.y + c2.y)*third);

        float* fin = fin_s + ln * 128;
        ((float2*)fin)[l] = at[m];
        ((float2*)(fin + 64))[l] = mn[m];
    }
    __syncwarp();

    float2 res[4];
    {
        float2 bv = ((const float2*)bres_s)[l];
#pragma unroll
        for (int m = 0; m < 4; m++) res[m] = bv;
    }
#pragma unroll 4
    for (int i = 0; i < 64; i += 2) {
        float2 wv0 = ((const float2*)(Wres_s + i * 64))[l];
        float2 wv1 = ((const float2*)(Wres_s + (i + 1) * 64))[l];
#pragma unroll
        for (int m = 0; m < 4; m++) {
            float2 xv = *(const float2*)(f0_s + (w * 4 + m) * 64 + i);
            res[m].x += xv.x * wv0.x + xv.y * wv1.x;
            res[m].y += xv.x * wv0.y + xv.y * wv1.y;
        }
    }

    float2 hf[4];
    {
        float2 bv = ((const float2*)bf1_s)[l];
#pragma unroll
        for (int m = 0; m < 4; m++) hf[m] = bv;
    }
#pragma unroll 4
    for (int i = 0; i < 128; i += 2) {
        float2 wv0 = ((const float2*)(Wf1_s + i * 64))[l];
        float2 wv1 = ((const float2*)(Wf1_s + (i + 1) * 64))[l];
#pragma unroll
        for (int m = 0; m < 4; m++) {
            float2 xv = *(const float2*)(fin_s + (w * 4 + m) * 128 + i);
            hf[m].x += xv.x * wv0.x + xv.y * wv1.x;
            hf[m].y += xv.x * wv0.y + xv.y * wv1.y;
        }
    }

    float2 w2v = ((const float2*)Wf2_s)[l];
    float bf2v = bf2[0];
#pragma unroll
    for (int m = 0; m < 4; m++) {
        float hx = fmaxf(hf[m].x, 0.f), hy = fmaxf(hf[m].y, 0.f);
        float fw = wsum(hx * w2v.x + hy * w2v.y) + bf2v;
        fw = 1.f / (1.f + expf(-fw));
        float2 fu = make_float2(0.1f*fw*at[m].x + (1.f - fw)*mn[m].x + 0.8f*res[m].x,
                                0.1f*fw*at[m].y + (1.f - fw)*mn[m].y + 0.8f*res[m].y);
        ((float2*)(fu_s + (w * 4 + m) * 64))[l] = fu;
    }
    __syncwarp();

    float2 gg[4];
    {
        float2 bv = ((const float2*)b3_s)[l];
#pragma unroll
        for (int m = 0; m < 4; m++) gg[m] = bv;
    }
#pragma unroll 4
    for (int i = 0; i < 64; i += 2) {
        float2 wv0 = ((const float2*)(W3_s + i * 64))[l];
        float2 wv1 = ((const float2*)(W3_s + (i + 1) * 64))[l];
#pragma unroll
        for (int m = 0; m < 4; m++) {
            float2 xv = *(const float2*)(fu_s + (w * 4 + m) * 64 + i);
            gg[m].x += xv.x * wv0.x + xv.y * wv1.x;
            gg[m].y += xv.x * wv0.y + xv.y * wv1.y;
        }
    }

    float4 w4v = ((const float4*)W4_s)[l];
    float b40 = b4[0], b41 = b4[1];
#pragma unroll
    for (int m = 0; m < 4; m++) {
        float gx = fmaxf(gg[m].x, 0.f), gy = fmaxf(gg[m].y, 0.f);
        float o0 = wsum(gx * w4v.x + gy * w4v.z) + b40;
        float o1 = wsum(gx * w4v.y + gy * w4v.w) + b41;
        int n = blockIdx.x * 32 + w * 4 + m;
        if (l == 0 && n < Nn) ((float2*)out)[n] = make_float2(o0, o1);
    }
}

// ---------------- stream/event setup ----------------
static cudaStream_t g_sideStream = 0;
static cudaEvent_t  g_evFork = 0, g_evScan = 0, g_evJoin = 0;
namespace {
struct HxStreamInit {
    HxStreamInit() {
        if (cudaStreamCreateWithFlags(&g_sideStream, cudaStreamNonBlocking) != cudaSuccess)
            g_sideStream = 0;
        if (cudaEventCreateWithFlags(&g_evFork, cudaEventDisableTiming) != cudaSuccess)
            g_evFork = 0;
        if (cudaEventCreateWithFlags(&g_evScan, cudaEventDisableTiming) != cudaSuccess)
            g_evScan = 0;
        if (cudaEventCreateWithFlags(&g_evJoin, cudaEventDisableTiming) != cudaSuccess)
            g_evJoin = 0;
    }
};
static HxStreamInit g_hxStreamInit;
}

// ---------------- launch ----------------
extern "C" void kernel_launch(void* const* d_in, const int* in_sizes, int n_in,
                              void* d_out, int out_size) {
    const float* in_feat = (const float*)d_in[0];
    const int*   src     = (const int*)d_in[1];
    const int*   dst     = (const int*)d_in[2];
    const float* W1   = (const float*)d_in[3];
    const float* b1   = (const float*)d_in[4];
    const float* W2   = (const float*)d_in[5];
    const float* b2   = (const float*)d_in[6];
    const float* Wres = (const float*)d_in[7];
    const float* bres = (const float*)d_in[8];
    const float* Wattn= (const float*)d_in[9];
    const float* battn= (const float*)d_in[10];
    const float* Wf1  = (const float*)d_in[11];
    const float* bf1  = (const float*)d_in[12];
    const float* Wf2  = (const float*)d_in[13];
    const float* bf2  = (const float*)d_in[14];
    const float* W3   = (const float*)d_in[15];
    const float* b3   = (const float*)d_in[16];
    const float* W4   = (const float*)d_in[17];
    const float* b4   = (const float*)d_in[18];
    float* out = (float*)d_out;

    const int FC_SMEM  = FC_SMEM_FLOATS * 4;
    const int FIN_SMEM = FIN_SMEM_FLOATS * 4;
    cudaFuncSetAttribute((const void*)k_fc,
                         cudaFuncAttributeMaxDynamicSharedMemorySize, FC_SMEM);
    cudaFuncSetAttribute((const void*)k_final,
                         cudaFuncAttributeMaxDynamicSharedMemorySize, FIN_SMEM);

    const int FC_GRID = Nn / 16;
    const int SFIN_GRID = (Nn / 4 + 1023) / 1024;   // 13
    bool par = (g_sideStream && g_evFork && g_evScan && g_evJoin);

    if (par) {
        cudaEventRecord(g_evFork, 0);
        cudaStreamWaitEvent(g_sideStream, g_evFork, 0);
        k_fc<<<FC_GRID, 256, FC_SMEM, g_sideStream>>>(in_feat, W1, b1, W2, b2);
        k_hist<<<(Ee / 4 + 255) / 256, 256>>>(dst);
        k_scan_partial<<<NSCAN, 1024>>>();
        k_scan_final<<<SFIN_GRID, 1024>>>();
        cudaEventRecord(g_evScan, 0);
        cudaStreamWaitEvent(g_sideStream, g_evScan, 0);
        k_make_s<<<(Nn * Hh / 4 + 255) / 256, 256, 0, g_sideStream>>>();
        k_scatter<<<(Ee / 4 + 255) / 256, 256>>>(src, dst);
        cudaEventRecord(g_evJoin, g_sideStream);
        cudaStreamWaitEvent(0, g_evJoin, 0);
    } else {
        k_hist<<<(Ee / 4 + 255) / 256, 256>>>(dst);
        k_scan_partial<<<NSCAN, 1024>>>();
        k_scan_final<<<SFIN_GRID, 1024>>>();
        k_scatter<<<(Ee / 4 + 255) / 256, 256>>>(src, dst);
        k_fc<<<FC_GRID, 256, FC_SMEM>>>(in_feat, W1, b1, W2, b2);
        k_make_s<<<(Nn * Hh / 4 + 255) / 256, 256>>>();
    }

    k_spmm<true><<<(Nn + 7) / 8, 256>>>();
    k_spmm<false><<<(Nn + 7) / 8, 256>>>();
    k_final<<<(Nn + 31) / 32, 256, FIN_SMEM>>>(Wres, bres, Wattn, battn,
                                               Wf1, bf1, Wf2, bf2,
                                               W3, b3, W4, b4, out);
}